// round 17
// baseline (speedup 1.0000x reference)
#include <cuda_runtime.h>
#include <cstdint>

// DetectionCriterion: B=32, T=25, H=W=128. Single fused kernel.
//   output:         [32, 125, 128, 128] f32  (ch 0..24 = cls, 25..124 = reg)
//   class_map:      [32,  25, 128, 128] i32  in {0,1,2}  -> cm = v-1
//   regression_map: [32, 100, 128, 128] f32
//   noise:          [32,  25, 128, 128] f32  uniform [0,1)
//
// Architecture: 800 blocks stream-scan (class_map, cls, noise), stash rare
// candidates (noise < 1/512; exactness: 128th-smallest ~9.4e-4 is 12 sigma
// below the cut) as (key, cls, precomputed-reg-loss). The reg smooth-L1 gather
// happens at stash time (R13). The LAST-finishing block of each batch b
// (per-batch ticket; writers __threadfence() before arriving) performs the
// exact strict-rank top-128 selection + loss for rows 2b, 2b+1; the globally
// last batch-tail folds the 32 partials into the output (R16 fusion).
// Selection exact: t = max{key : strict_rank < 128} = 128th order statistic;
// kk <= t keeps ties (matches `scores <= thresh`, incl. keep-all when n<=128).
//
// State invariant: all __device__ globals zero at load; every call restores
// them (tails reset g_cnt rows, g_done_b[b]; last tail resets g_done).

#define NB 32
#define ELEMS_PER_B (25 * 128 * 128)      // 409600
#define OUT_STRIDE_B (125 * 16384)        // 2048000
#define REG_STRIDE_B (100 * 16384)        // 1638400
#define CAP 1024                          // stash capacity per (b, class); mean ~267
#define SEL_CAP 512                       // selection scan width (15 sigma above mean)
#define STAGE_CAP 128                     // per-block staging per class; mean ~11
#define K_SAMPLE 128
// drop if softplus(-cls*cm) < 0.03  <=>  -cls*cm < ln(e^0.03 - 1)
#define MINING_CUT (-3.4915206f)
// stash everything with noise < 1/512 (bits < 0x3B000000)
#define STASH_BITS 0x3B000000u

__device__ int      g_cnt[NB * 2];        // zero at load; restored each call
__device__ unsigned g_key[NB * 2 * CAP];
__device__ float    g_cls[NB * 2 * CAP];
__device__ float    g_reg[NB * 2 * CAP];  // precomputed smooth-L1 sum (pos only)
__device__ double   g_partial[NB];
__device__ int      g_done_b[NB];         // per-batch completion tickets
__device__ int      g_done;               // batch-tail completion ticket

__device__ __forceinline__ float smooth_l1_4(const float* rp, const float* gp) {
    float rl = 0.0f;
    #pragma unroll
    for (int q = 0; q < 4; ++q) {
        const float d = __ldg(&rp[q * ELEMS_PER_B]) - __ldg(&gp[q * ELEMS_PER_B]);
        const float ad = fabsf(d);
        rl += (ad < 1.0f) ? 0.5f * d * d : ad - 0.5f;
    }
    return rl;
}

// Grid: (25, 32), 256 threads; 16384 elements per block via float4/int4 loads.
__global__ __launch_bounds__(256) void fused_kernel(
    const float* __restrict__ out,
    const int* __restrict__ cmap,
    const float* __restrict__ rmap,
    const float* __restrict__ noise,
    float* __restrict__ outp)
{
    const int b = blockIdx.y;
    const int tid = threadIdx.x;

    __shared__ int      s_cnt[2];
    __shared__ int      s_base[2];
    __shared__ unsigned s_key[2][STAGE_CAP];
    __shared__ unsigned s_idx[2][STAGE_CAP];
    __shared__ float    s_cls[2][STAGE_CAP];
    // tail-phase storage
    __shared__ unsigned t_keys[SEL_CAP];
    __shared__ unsigned t_mx[8];
    __shared__ double   t_red[8];
    __shared__ int      s_ticket;
    __shared__ bool     t_last;

    if (tid < 2) s_cnt[tid] = 0;
    __syncthreads();

    const int base = blockIdx.x * 16384;
    const int4*   cm4 = (const int4*)  (cmap  + (size_t)b * ELEMS_PER_B + base);
    const float4* cl4 = (const float4*)(out   + (size_t)b * OUT_STRIDE_B + base);
    const float4* nz4 = (const float4*)(noise + (size_t)b * ELEMS_PER_B + base);

    const float* outb = out  + (size_t)b * OUT_STRIDE_B;
    const float* rmb  = rmap + (size_t)b * REG_STRIDE_B;

    // ---- Phase 1: stream scan + stash ----
    #pragma unroll 8
    for (int it = 0; it < 16; ++it) {
        const int v = it * 256 + tid;
        const int4   cm = __ldg(&cm4[v]);
        const float4 cl = __ldg(&cl4[v]);
        const float4 nz = __ldg(&nz4[v]);

        const int   cma[4] = {cm.x - 1, cm.y - 1, cm.z - 1, cm.w - 1};
        const float cla[4] = {cl.x, cl.y, cl.z, cl.w};
        const float nza[4] = {nz.x, nz.y, nz.z, nz.w};

        #pragma unroll
        for (int j = 0; j < 4; ++j) {
            const int cmv = cma[j];
            if (cmv == 0) continue;
            const float cls = cla[j];
            const float z = -cls * (float)cmv;
            if (z < MINING_CUT) continue;                 // mined out
            const unsigned bits = __float_as_uint(nza[j]);
            if (bits >= STASH_BITS) continue;             // can't be in top-128
            const int c = (cmv == 1) ? 0 : 1;
            const unsigned idx = (unsigned)(base + v * 4 + j);
            const int slot = atomicAdd(&s_cnt[c], 1);
            if (slot < STAGE_CAP) {
                s_key[c][slot] = bits; s_idx[c][slot] = idx; s_cls[c][slot] = cls;
            } else {  // staging overflow (statistically never): spill direct
                const int g = atomicAdd(&g_cnt[b * 2 + c], 1);
                if (g < CAP) {
                    const size_t o = (size_t)(b * 2 + c) * CAP + g;
                    float rl = 0.0f;
                    if (c == 0) {
                        const int tmpl = idx >> 14, hw = idx & 16383;
                        rl = smooth_l1_4(outb + (25 + tmpl) * 16384 + hw,
                                         rmb  + tmpl * 16384 + hw);
                    }
                    g_key[o] = bits; g_cls[o] = cls; g_reg[o] = rl;
                }
            }
        }
    }
    __syncthreads();

    // ---- Phase 2: writeback stash (reg loss gathered here for positives) ----
    if (tid < 2) {
        int m = s_cnt[tid]; if (m > STAGE_CAP) m = STAGE_CAP;
        s_base[tid] = atomicAdd(&g_cnt[b * 2 + tid], m);
    }
    __syncthreads();

    #pragma unroll
    for (int c = 0; c < 2; ++c) {
        int m = s_cnt[c]; if (m > STAGE_CAP) m = STAGE_CAP;
        for (int i = tid; i < m; i += 256) {
            const int g = s_base[c] + i;
            if (g < CAP) {
                const size_t o = (size_t)(b * 2 + c) * CAP + g;
                float rl = 0.0f;
                if (c == 0) {
                    const unsigned idx = s_idx[c][i];
                    const int tmpl = idx >> 14, hw = idx & 16383;
                    rl = smooth_l1_4(outb + (25 + tmpl) * 16384 + hw,
                                     rmb  + tmpl * 16384 + hw);
                }
                g_key[o] = s_key[c][i]; g_cls[o] = s_cls[c][i]; g_reg[o] = rl;
            }
        }
    }

    // ---- Phase 3: per-batch tail — last of the 25 blocks does selection ----
    __threadfence();                       // publish stash before ticketing
    __syncthreads();                       // all threads' writes issued
    if (tid == 0) s_ticket = atomicAdd(&g_done_b[b], 1);
    __syncthreads();
    if (s_ticket != 24) return;            // not the batch tail

    if (tid == 0) g_done_b[b] = 0;         // restore invariant
    const int wid = tid >> 5, lane = tid & 31;
    double lsum = 0.0;

    #pragma unroll
    for (int cc = 0; cc < 2; ++cc) {
        const int bc = b * 2 + cc;
        const size_t rowo = (size_t)bc * CAP;

        t_keys[tid]       = g_key[rowo + tid];
        t_keys[tid + 256] = g_key[rowo + tid + 256];
        int n = g_cnt[bc]; if (n > SEL_CAP) n = SEL_CAP;  // 15 sigma: never clamps
        __syncthreads();

        // strict rank of my two slots; threshold candidate = max{key: rank<K}
        unsigned tl = 0;
        #pragma unroll
        for (int s = 0; s < 2; ++s) {
            const int i = tid + s * 256;
            if (i < n) {
                const unsigned kk = t_keys[i];
                int l0 = 0, l1 = 0;
                int j = 0;
                for (; j + 2 <= n; j += 2) {
                    l0 += (t_keys[j]     < kk) ? 1 : 0;
                    l1 += (t_keys[j + 1] < kk) ? 1 : 0;
                }
                for (; j < n; ++j) l0 += (t_keys[j] < kk) ? 1 : 0;
                if (l0 + l1 < K_SAMPLE && kk > tl) tl = kk;
            }
        }
        tl = __reduce_max_sync(0xFFFFFFFFu, tl);
        if (lane == 0) t_mx[wid] = tl;
        __syncthreads();
        if (tid < 32) {
            unsigned v = (tid < 8) ? t_mx[tid] : 0u;
            v = __reduce_max_sync(0xFFFFFFFFu, v);
            if (tid == 0) t_mx[0] = v;
        }
        __syncthreads();
        const unsigned t = t_mx[0];

        // loss for kept candidates (noise <= thresh, ties kept)
        const float sgn = (cc == 0) ? 1.0f : -1.0f;
        #pragma unroll
        for (int s = 0; s < 2; ++s) {
            const int i = tid + s * 256;
            if (i < n && t_keys[i] <= t) {
                const float cls = g_cls[rowo + i];
                lsum += (double)log1pf(expf(-cls * sgn));      // softplus
                if (cc == 0) lsum += 2.0 * (double)g_reg[rowo + i];
            }
        }
        __syncthreads();                    // t_keys reuse + g_cnt reset safety
        if (tid == 0) g_cnt[bc] = 0;        // restore invariant
    }

    // block-reduce the batch loss (8 warps)
    #pragma unroll
    for (int off = 16; off > 0; off >>= 1)
        lsum += __shfl_down_sync(0xFFFFFFFFu, lsum, off);
    if (lane == 0) t_red[wid] = lsum;
    __syncthreads();
    if (tid < 32) {
        double v = (tid < 8) ? t_red[tid] : 0.0;
        #pragma unroll
        for (int off = 4; off > 0; off >>= 1)
            v += __shfl_down_sync(0xFFFFFFFFu, v, off);
        if (tid == 0) {
            g_partial[b] = v;
            __threadfence();                // publish before signaling done
            t_last = (atomicAdd(&g_done, 1) == NB - 1);
        }
    }
    __syncthreads();

    // ---- Phase 4: globally last batch-tail folds 32 partials ----
    if (t_last && tid < 32) {
        double v = g_partial[tid];
        #pragma unroll
        for (int off = 16; off > 0; off >>= 1)
            v += __shfl_down_sync(0xFFFFFFFFu, v, off);
        if (tid == 0) {
            outp[0] = (float)v;
            g_done = 0;                     // restore invariant
        }
    }
}

extern "C" void kernel_launch(void* const* d_in, const int* in_sizes, int n_in,
                              void* d_out, int out_size) {
    const float* output = (const float*)d_in[0];
    const int*   cmap   = (const int*)  d_in[1];
    const float* rmap   = (const float*)d_in[2];
    const float* noise  = (const float*)d_in[3];
    float* outp = (float*)d_out;

    dim3 g1(25, 32);
    fused_kernel<<<g1, 256>>>(output, cmap, rmap, noise, outp);
}